// round 13
// baseline (speedup 1.0000x reference)
#include <cuda_runtime.h>

#define N_MET_MAX 100000
#define N_RXN_MAX 50000
#define HID 32
#define MSGD 16

typedef unsigned long long ull;

// Scratch: per-reaction accumulated message [N_RXN, MSGD].
__device__ __align__(16) float g_hrxn[N_RXN_MAX * MSGD];

// ---- packed f32x2 helpers (sm_103a FFMA2; ptxas won't auto-fuse) ----
__device__ __forceinline__ void fma2(ull& d, ull a, ull b, ull c) {
    asm("fma.rn.f32x2 %0, %1, %2, %3;" : "=l"(d) : "l"(a), "l"(b), "l"(c));
}
__device__ __forceinline__ ull pack2(float lo, float hi) {
    ull p; asm("mov.b64 %0, {%1, %2};" : "=l"(p) : "f"(lo), "f"(hi)); return p;
}
__device__ __forceinline__ void unpack2(float& lo, float& hi, ull p) {
    asm("mov.b64 {%0, %1}, %2;" : "=f"(lo), "=f"(hi) : "l"(p));
}

// Exact-form paired tanh: 2 tanh with 3 MUFU (2 ex2 + 1 shared rcp).
// tanh(x) = 1 - 2/(1+e^{2x}); correct saturation both tails, rel err ~1e-6.
// (This math measured rel_err=2.8e-7 end-to-end in the round-4 bench.)
__device__ __forceinline__ void tanh2(ull a2, float& tlo, float& thi) {
    float alo, ahi; unpack2(alo, ahi, a2);
    const float K = 2.885390082f;               // 2*log2(e)
    float mlo = fminf(K * alo, 126.0f);
    float mhi = fminf(K * ahi, 126.0f);
    float elo, ehi;
    asm("ex2.approx.f32 %0, %1;" : "=f"(elo) : "f"(mlo));
    asm("ex2.approx.f32 %0, %1;" : "=f"(ehi) : "f"(mhi));
    float dlo = 1.0f + elo, dhi = 1.0f + ehi;
    float r;                                    // r = 1/(dlo*dhi)
    asm("rcp.approx.f32 %0, %1;" : "=f"(r) : "f"(dlo * dhi));
    tlo = fmaf(-2.0f, dhi * r, 1.0f);
    thi = fmaf(-2.0f, dlo * r, 1.0f);
}

// ---------------------------------------------------------------------------
// Kernel 0: zero g_hrxn scratch and dxdt (d_out poisoned 0xAA each replay).
// ---------------------------------------------------------------------------
__global__ void zero_kernel(float4* __restrict__ dxdt4, int n_met4, int n_hrxn4) {
    int i = blockIdx.x * blockDim.x + threadIdx.x;
    float4 z = make_float4(0.f, 0.f, 0.f, 0.f);
    if (i < n_hrxn4) reinterpret_cast<float4*>(g_hrxn)[i] = z;
    if (i < n_met4)  dxdt4[i] = z;
}

// ---------------------------------------------------------------------------
// Kernel 1: per substrate edge: layer1 (packed) -> paired exact tanh ->
// msg = h@W2+b2 (packed FFMA2, b2 folded into acc init) -> 4x red.v4.
// ---------------------------------------------------------------------------
__global__ __launch_bounds__(256) void msg_kernel(
    const float* __restrict__ x_met,
    const float* __restrict__ sto_sub,
    const int*   __restrict__ met_sub,
    const int*   __restrict__ rxn_sub,
    const float* __restrict__ W1m,  // [2, HID] row-major
    const float* __restrict__ b1m,  // [HID]
    const float* __restrict__ W2m,  // [HID, MSGD] row-major
    const float* __restrict__ b2m,  // [MSGD]
    int E)
{
    __shared__ __align__(16) ull  sW1x2[HID / 2];   // pairs of W1m[0][*]
    __shared__ __align__(16) ull  sW1s2[HID / 2];   // pairs of W1m[1][*]
    __shared__ __align__(16) ull  sB12[HID / 2];    // pairs of b1m[*]
    __shared__ __align__(16) float sW2[HID * MSGD];
    __shared__ __align__(16) float sB2[MSGD];

    if (threadIdx.x < HID / 2) {
        sW1x2[threadIdx.x] = reinterpret_cast<const ull*>(W1m)[threadIdx.x];
        sW1s2[threadIdx.x] = reinterpret_cast<const ull*>(W1m + HID)[threadIdx.x];
        sB12[threadIdx.x]  = reinterpret_cast<const ull*>(b1m)[threadIdx.x];
    }
    for (int i = threadIdx.x; i < HID * MSGD; i += blockDim.x)
        sW2[i] = W2m[i];
    if (threadIdx.x < MSGD) sB2[threadIdx.x] = b2m[threadIdx.x];
    __syncthreads();

    int e = blockIdx.x * blockDim.x + threadIdx.x;
    if (e >= E) return;

    float x = __ldg(&x_met[met_sub[e]]);   // random gather, L2-resident (400KB)
    float s = sto_sub[e];
    ull x2 = pack2(x, x);
    ull s2 = pack2(s, s);

    // Layer 1 + paired exact tanh -> th[32]
    float th[HID];
#pragma unroll
    for (int q = 0; q < HID / 2; q++) {
        ull a2;
        fma2(a2, s2, sW1s2[q], sB12[q]);
        fma2(a2, x2, sW1x2[q], a2);
        tanh2(a2, th[2 * q], th[2 * q + 1]);
    }

    // msg[16] = th @ W2 + b2, packed accumulators (8 FFMA2 per k).
    ull acc[MSGD / 2];
    {
        const ull* b2p = reinterpret_cast<const ull*>(sB2);
#pragma unroll
        for (int q = 0; q < MSGD / 2; q++) acc[q] = b2p[q];
    }
#pragma unroll
    for (int k = 0; k < HID; k++) {
        ull hk = pack2(th[k], th[k]);
        const ulonglong2* w = reinterpret_cast<const ulonglong2*>(&sW2[k * MSGD]);
#pragma unroll
        for (int q = 0; q < 4; q++) {
            ulonglong2 wv = w[q];                 // broadcast LDS.128
            fma2(acc[2*q+0], hk, wv.x, acc[2*q+0]);
            fma2(acc[2*q+1], hk, wv.y, acc[2*q+1]);
        }
    }

    float m[MSGD];
#pragma unroll
    for (int q = 0; q < MSGD / 2; q++) unpack2(m[2*q], m[2*q+1], acc[q]);

    float* dst = &g_hrxn[(size_t)rxn_sub[e] * MSGD];
#pragma unroll
    for (int q = 0; q < 4; q++) {
        asm volatile("red.global.add.v4.f32 [%0], {%1, %2, %3, %4};"
                     :: "l"(dst + 4 * q),
                        "f"(m[4*q+0]), "f"(m[4*q+1]),
                        "f"(m[4*q+2]), "f"(m[4*q+3])
                     : "memory");
    }
}

// ---------------------------------------------------------------------------
// Kernel 2: per reaction, v = softplus(Lin(tanh(Lin(h_rxn, 16->32)), 32->1)).
// ---------------------------------------------------------------------------
__global__ __launch_bounds__(256) void rate_kernel(
    const float* __restrict__ W1r,  // [MSGD, HID] row-major
    const float* __restrict__ b1r,  // [HID]
    const float* __restrict__ W2r,  // [HID, 1]
    const float* __restrict__ b2r,  // [1]
    float* __restrict__ v_out,
    int n_rxn)
{
    __shared__ __align__(16) float sW1r[MSGD * HID];
    __shared__ __align__(16) ull   sB1r2[HID / 2];
    __shared__ float sW2r[HID], sB2r;

    for (int i = threadIdx.x; i < MSGD * HID; i += blockDim.x) sW1r[i] = W1r[i];
    if (threadIdx.x < HID / 2)
        sB1r2[threadIdx.x] = reinterpret_cast<const ull*>(b1r)[threadIdx.x];
    if (threadIdx.x < HID) sW2r[threadIdx.x] = W2r[threadIdx.x];
    if (threadIdx.x == 0) sB2r = b2r[0];
    __syncthreads();

    int r = blockIdx.x * blockDim.x + threadIdx.x;
    if (r >= n_rxn) return;

    float h[MSGD];
    const float4* hr = reinterpret_cast<const float4*>(&g_hrxn[(size_t)r * MSGD]);
#pragma unroll
    for (int q = 0; q < 4; q++) {
        float4 hv = hr[q];
        h[4*q+0] = hv.x; h[4*q+1] = hv.y; h[4*q+2] = hv.z; h[4*q+3] = hv.w;
    }

    // a[32] = h @ W1r + b1r over packed j-pairs, exact tanh, dot with W2r.
    float acc = sB2r;
#pragma unroll
    for (int q = 0; q < HID / 2; q++) {
        ull a2 = sB1r2[q];
#pragma unroll
        for (int d = 0; d < MSGD; d++) {
            ull w = reinterpret_cast<const ull*>(&sW1r[d * HID])[q];
            fma2(a2, pack2(h[d], h[d]), w, a2);
        }
        float tl, thh;
        tanh2(a2, tl, thh);
        acc = fmaf(tl,  sW2r[2*q],     acc);
        acc = fmaf(thh, sW2r[2*q + 1], acc);
    }

    // softplus(acc) = max(acc,0) + log1p(exp(-|acc|)) — stable both tails
    float sp = fmaxf(acc, 0.0f) + log1pf(__expf(-fabsf(acc)));
    v_out[r] = sp;
}

// ---------------------------------------------------------------------------
// Kernel 3: 8 edges/thread. Front-batch 6 LDG.128 + 8 gathers for deep MLP
// (issue=3.7% last profile -> latency bound; widen in-flight window).
// ---------------------------------------------------------------------------
__global__ __launch_bounds__(256) void scatter_kernel(
    const float* __restrict__ sto_all,
    const int*   __restrict__ met_all,
    const int*   __restrict__ rxn_all,
    const float* __restrict__ v,
    float*       __restrict__ dxdt,
    int E)
{
    int t = blockIdx.x * blockDim.x + threadIdx.x;
    int e = t * 8;
    if (e + 7 < E) {
        // 6 independent LDG.128 issued back-to-back.
        float4 s4a = *reinterpret_cast<const float4*>(sto_all + e);
        float4 s4b = *reinterpret_cast<const float4*>(sto_all + e + 4);
        int4   m4a = *reinterpret_cast<const int4*>(met_all + e);
        int4   m4b = *reinterpret_cast<const int4*>(met_all + e + 4);
        int4   r4a = *reinterpret_cast<const int4*>(rxn_all + e);
        int4   r4b = *reinterpret_cast<const int4*>(rxn_all + e + 4);
        // 8 independent gathers (L2-resident v, 200KB).
        float va0 = __ldg(&v[r4a.x]), va1 = __ldg(&v[r4a.y]);
        float va2 = __ldg(&v[r4a.z]), va3 = __ldg(&v[r4a.w]);
        float vb0 = __ldg(&v[r4b.x]), vb1 = __ldg(&v[r4b.y]);
        float vb2 = __ldg(&v[r4b.z]), vb3 = __ldg(&v[r4b.w]);
        atomicAdd(&dxdt[m4a.x], s4a.x * va0);
        atomicAdd(&dxdt[m4a.y], s4a.y * va1);
        atomicAdd(&dxdt[m4a.z], s4a.z * va2);
        atomicAdd(&dxdt[m4a.w], s4a.w * va3);
        atomicAdd(&dxdt[m4b.x], s4b.x * vb0);
        atomicAdd(&dxdt[m4b.y], s4b.y * vb1);
        atomicAdd(&dxdt[m4b.z], s4b.z * vb2);
        atomicAdd(&dxdt[m4b.w], s4b.w * vb3);
    } else {
        for (; e < E; e++) {
            float c = sto_all[e] * __ldg(&v[rxn_all[e]]);
            atomicAdd(&dxdt[met_all[e]], c);
        }
    }
}

// ---------------------------------------------------------------------------
// Launch. Output layout: d_out = [dxdt (n_met) | v (n_rxn)].
// ---------------------------------------------------------------------------
extern "C" void kernel_launch(void* const* d_in, const int* in_sizes, int n_in,
                              void* d_out, int out_size)
{
    const float* x_met   = (const float*)d_in[0];
    const float* sto_sub = (const float*)d_in[1];
    const float* sto_all = (const float*)d_in[2];
    const float* W1m     = (const float*)d_in[3];
    const float* b1m     = (const float*)d_in[4];
    const float* W2m     = (const float*)d_in[5];
    const float* b2m     = (const float*)d_in[6];
    const float* W1r     = (const float*)d_in[7];
    const float* b1r     = (const float*)d_in[8];
    const float* W2r     = (const float*)d_in[9];
    const float* b2r     = (const float*)d_in[10];
    const int*   met_sub = (const int*)d_in[11];
    const int*   rxn_sub = (const int*)d_in[12];
    const int*   met_all = (const int*)d_in[13];
    const int*   rxn_all = (const int*)d_in[14];

    int n_met = in_sizes[0];
    int e_sub = in_sizes[1];
    int e_all = in_sizes[2];
    int n_rxn = out_size - n_met;

    float* dxdt  = (float*)d_out;
    float* v_out = (float*)d_out + n_met;

    int n_hrxn4 = n_rxn * MSGD / 4;
    int n_met4  = n_met / 4;               // n_met = 100000, divisible by 4
    int zn = n_hrxn4 > n_met4 ? n_hrxn4 : n_met4;

    zero_kernel<<<(zn + 255) / 256, 256>>>((float4*)dxdt, n_met4, n_hrxn4);
    msg_kernel<<<(e_sub + 255) / 256, 256>>>(x_met, sto_sub, met_sub, rxn_sub,
                                             W1m, b1m, W2m, b2m, e_sub);
    rate_kernel<<<(n_rxn + 255) / 256, 256>>>(W1r, b1r, W2r, b2r, v_out, n_rxn);
    int q = (e_all + 7) / 8;
    scatter_kernel<<<(q + 255) / 256, 256>>>(sto_all, met_all, rxn_all,
                                             v_out, dxdt, e_all);
}